// round 1
// baseline (speedup 1.0000x reference)
#include <cuda_runtime.h>

#define B_ROWS      8192
#define FEATURE_NUM 200
#define NUMERIC_SZ  100
#define IN_W        (FEATURE_NUM + NUMERIC_SZ)   // 300
#define EMBED       64
#define ROWS_PB     4

__global__ __launch_bounds__(EMBED * ROWS_PB)
void fm_kernel(const float* __restrict__ inputs,
               const float* __restrict__ w_one_hot,
               const float* __restrict__ w_numeric,
               const float* __restrict__ v_one_hot,
               const float* __restrict__ v_numeric,
               const float* __restrict__ bias,
               float* __restrict__ out)
{
    __shared__ int   s_idx[ROWS_PB][FEATURE_NUM];
    __shared__ float s_num[ROWS_PB][NUMERIC_SZ];
    __shared__ float s_wpart[ROWS_PB][2];

    const int e   = threadIdx.x;          // 0..63 : embed dim
    const int r   = threadIdx.y;          // 0..3  : row within block
    const int row = blockIdx.x * ROWS_PB + r;

    const float* in_row = inputs + (long)row * IN_W;

    // Stage indices (cast float->int) and numeric features into shared.
    #pragma unroll
    for (int j = e; j < FEATURE_NUM; j += EMBED)
        s_idx[r][j] = (int)in_row[j];
    #pragma unroll
    for (int k = e; k < NUMERIC_SZ; k += EMBED)
        s_num[r][k] = in_row[FEATURE_NUM + k];
    __syncthreads();

    // ---- sparse gather: sum and sum-of-squares over 200 embedding rows ----
    float s = 0.f, ss = 0.f;
    #pragma unroll 8
    for (int j = 0; j < FEATURE_NUM; j++) {
        int id = s_idx[r][j];
        float v = __ldg(&v_one_hot[id * EMBED + e]);   // coalesced 256B per row
        s  += v;
        ss  = fmaf(v, v, ss);
    }

    // ---- first-order sparse part: each thread sums a strided subset ----
    float fo = 0.f;
    #pragma unroll
    for (int j = e; j < FEATURE_NUM; j += EMBED)
        fo += __ldg(&w_one_hot[s_idx[r][j]]);          // 4MB table, L2-resident

    // ---- dense numeric part ----
    #pragma unroll 4
    for (int k = 0; k < NUMERIC_SZ; k++) {
        float n  = s_num[r][k];
        float vn = __ldg(&v_numeric[k * EMBED + e]);   // 25.6KB, L1-resident
        float t  = n * vn;
        s  += t;
        ss  = fmaf(t, t, ss);
    }
    #pragma unroll
    for (int k = e; k < NUMERIC_SZ; k += EMBED)
        fo = fmaf(s_num[r][k], __ldg(&w_numeric[k]), fo);

    // ---- combine + reduce over the 64 threads of this row (2 warps) ----
    float val = fmaf(0.5f, fmaf(s, s, -ss), fo);

    #pragma unroll
    for (int off = 16; off > 0; off >>= 1)
        val += __shfl_down_sync(0xffffffffu, val, off);

    const int lane = e & 31;
    const int warp = e >> 5;
    if (lane == 0) s_wpart[r][warp] = val;
    __syncthreads();

    if (e == 0)
        out[row] = s_wpart[r][0] + s_wpart[r][1] + bias[0];
}

extern "C" void kernel_launch(void* const* d_in, const int* in_sizes, int n_in,
                              void* d_out, int out_size)
{
    const float* inputs    = (const float*)d_in[0];
    const float* w_one_hot = (const float*)d_in[1];
    const float* w_numeric = (const float*)d_in[2];
    const float* v_one_hot = (const float*)d_in[3];
    const float* v_numeric = (const float*)d_in[4];
    const float* bias      = (const float*)d_in[5];
    float* out = (float*)d_out;

    dim3 block(EMBED, ROWS_PB);
    dim3 grid(B_ROWS / ROWS_PB);
    fm_kernel<<<grid, block>>>(inputs, w_one_hot, w_numeric,
                               v_one_hot, v_numeric, bias, out);
}